// round 6
// baseline (speedup 1.0000x reference)
#include <cuda_runtime.h>
#include <cuda_bf16.h>
#include <math.h>

// ---------------- problem constants ----------------
#define BB 4
#define CC 64
#define HH 128
#define WW 128
#define EE 32
#define HW (HH*WW)              // 16384
#define NPIX (BB*HW)            // 65536
#define NASSIGN (NPIX*2)        // 131072
#define PADW 130
#define PADIMG (PADW*PADW)      // 16900
#define NPADROW (BB*PADIMG)     // 67600
#define MAXTILES 544            // sum ceil(cnt_e/256) <= 543

// per-expert B fragments: 9 taps * 4 kc * 8 nb * 32 lanes uint4 {h0,h1,l0,l1}
#define WF4E 9216

// conv smem layout (byte offsets). A rows padded to 144B (16r mod 128 distinct).
#define AHI_OFF 0u              // 256 rows * 144B = 36864
#define ALO_OFF 36864u          // 36864
#define BF_OFF  73728u          // 16384 (one tap, hi/lo interleaved uint4)
#define PR_OFF  90112u          // int[256]
#define GW_OFF  91136u          // float[256]
#define BIAS_OFF 92160u         // float[64]
#define CONV_SMEM 92416u

// ---------------- device scratch ----------------
__device__ __nv_bfloat16 g_x_hi[NPADROW * CC];
__device__ __nv_bfloat16 g_x_lo[NPADROW * CC];
__device__ uint4 g_wf[EE * WF4E];        // pre-permuted B fragments {h0,h1,l0,l1}
__device__ int   g_top_idx[NPIX * 2];
__device__ float g_top_w[NPIX * 2];
__device__ int   g_cnt[EE];
__device__ int   g_base[EE];
__device__ int   g_cursor[EE];
__device__ int   g_tileStart[EE + 1];
__device__ int   g_listPix[NASSIGN];
__device__ float g_listW[NASSIGN];

__device__ __forceinline__ unsigned short bfbits(__nv_bfloat16 h) {
    return *reinterpret_cast<unsigned short*>(&h);
}

// ---------------- init ----------------
__global__ void k_init(float* out, int n) {
    int i = blockIdx.x * blockDim.x + threadIdx.x;
    if (i < n) out[i] = 0.0f;
    if (blockIdx.x == 0 && threadIdx.x < EE) {
        g_cnt[threadIdx.x] = 0;
        g_cursor[threadIdx.x] = 0;
    }
}

// ---------------- x -> padded channels-last bf16 hi/lo ----------------
__global__ void k_tx(const float* __restrict__ x) {
    __shared__ float s[CC][33];
    int b = blockIdx.y;
    int hw0 = blockIdx.x * 32;
    int tx = threadIdx.x, ty = threadIdx.y;
    for (int c = ty; c < CC; c += 8)
        s[c][tx] = x[((size_t)(b * CC + c) << 14) + hw0 + tx];
    __syncthreads();
    int t = ty * 32 + tx;
    int y = hw0 >> 7, x0 = hw0 & 127;
    unsigned* hi32 = (unsigned*)g_x_hi;
    unsigned* lo32 = (unsigned*)g_x_lo;
    for (int k = t; k < 32 * 32; k += 256) {
        int p = k >> 5, cp = k & 31;
        int row = b * PADIMG + (y + 1) * PADW + (x0 + p + 1);
        float a = s[2 * cp][p], bv = s[2 * cp + 1][p];
        __nv_bfloat16 ha = __float2bfloat16_rn(a), hb = __float2bfloat16_rn(bv);
        float la = a - __bfloat162float(ha), lb = bv - __bfloat162float(hb);
        __nv_bfloat16 hla = __float2bfloat16_rn(la), hlb = __float2bfloat16_rn(lb);
        hi32[row * 32 + cp] = ((unsigned)bfbits(hb) << 16) | bfbits(ha);
        lo32[row * 32 + cp] = ((unsigned)bfbits(hlb) << 16) | bfbits(hla);
    }
}

// ---------------- zero the halo rows ----------------
__global__ void k_border() {
    int w = blockIdx.x * 256 + threadIdx.x;
    if (w >= NPADROW * 32) return;
    int p = w >> 5;
    int r = p % PADIMG;
    int y = r / PADW, xx = r % PADW;
    if (y == 0 || y == PADW - 1 || xx == 0 || xx == PADW - 1) {
        ((unsigned*)g_x_hi)[w] = 0u;
        ((unsigned*)g_x_lo)[w] = 0u;
    }
}

// ---------------- weights -> pre-permuted interleaved B fragments ----------------
// uint4 index: ((e*9 + t)*4*8 + kc*8 + nb)*32 + lane
// holds {h(k0,k1), h(k8,k9), l(k0,k1), l(k8,k9)} at co = nb*8+lane/4, k-pairs 2(lane%4)
__global__ void k_tw(const float* __restrict__ w) {
    int i = blockIdx.x * 256 + threadIdx.x;
    if (i >= EE * WF4E) return;
    int e = i / WF4E;
    int r = i % WF4E;
    int t = r >> 10;  r &= 1023;
    int kc = r >> 8;  r &= 255;
    int nb = r >> 5;
    int lane = r & 31;
    int co  = nb * 8 + (lane >> 2);
    int ci0 = kc * 16 + 2 * (lane & 3);
    const float* wp = w + (size_t)(((e << 6) | co) << 6) * 9 + t;
    float v00 = wp[(ci0)     * 9], v01 = wp[(ci0 + 1) * 9];
    float v10 = wp[(ci0 + 8) * 9], v11 = wp[(ci0 + 9) * 9];
    __nv_bfloat16 h00 = __float2bfloat16_rn(v00), h01 = __float2bfloat16_rn(v01);
    __nv_bfloat16 h10 = __float2bfloat16_rn(v10), h11 = __float2bfloat16_rn(v11);
    uint4 o;
    o.x = ((unsigned)bfbits(h01) << 16) | bfbits(h00);
    o.y = ((unsigned)bfbits(h11) << 16) | bfbits(h10);
    o.z = ((unsigned)bfbits(__float2bfloat16_rn(v01 - __bfloat162float(h01))) << 16)
        | bfbits(__float2bfloat16_rn(v00 - __bfloat162float(h00)));
    o.w = ((unsigned)bfbits(__float2bfloat16_rn(v11 - __bfloat162float(h11))) << 16)
        | bfbits(__float2bfloat16_rn(v10 - __bfloat162float(h10)));
    g_wf[i] = o;
}

// ---------------- gate (fp32, smem-staged) ----------------
__global__ void __launch_bounds__(256) k_gate(const float* __restrict__ x,
                                              const float* __restrict__ gw,
                                              const float* __restrict__ gb) {
    __shared__ float gws[EE * CC];
    __shared__ float gbs[EE];
    __shared__ float xs[16][256];
    int tid = threadIdx.x;
    for (int i = tid; i < EE * CC; i += 256) gws[i] = gw[i];
    if (tid < EE) gbs[tid] = gb[tid];

    int pix0 = blockIdx.x * 256;
    int b = pix0 >> 14, hw0 = pix0 & (HW - 1);

    float lg[EE];
#pragma unroll
    for (int e = 0; e < EE; e++) lg[e] = 0.0f;

    for (int c0 = 0; c0 < CC; c0 += 16) {
        __syncthreads();
        for (int i = tid; i < 16 * 256; i += 256)
            xs[i >> 8][tid] = x[((size_t)(b * CC + c0 + (i >> 8)) << 14) + hw0 + tid];
        __syncthreads();
#pragma unroll 4
        for (int c = 0; c < 16; c++) {
            float xv = xs[c][tid];
#pragma unroll
            for (int e = 0; e < EE; e++)
                lg[e] = fmaf(xv, gws[(e << 6) + c0 + c], lg[e]);
        }
    }
#pragma unroll
    for (int e = 0; e < EE; e++) lg[e] += gbs[e];

    float v1 = -1e30f; int i1 = 0;
#pragma unroll
    for (int e = 0; e < EE; e++) if (lg[e] > v1) { v1 = lg[e]; i1 = e; }
    float v2 = -1e30f; int i2 = 0;
#pragma unroll
    for (int e = 0; e < EE; e++) if (e != i1 && lg[e] > v2) { v2 = lg[e]; i2 = e; }

    float d = expf(v2 - v1);
    float s = 1.0f / (1.0f + d);
    int pix = pix0 + tid;
    g_top_idx[pix * 2]     = i1;
    g_top_idx[pix * 2 + 1] = i2;
    g_top_w[pix * 2]       = s;
    g_top_w[pix * 2 + 1]   = d * s;
    atomicAdd(&g_cnt[i1], 1);
    atomicAdd(&g_cnt[i2], 1);
}

// ---------------- prefix ----------------
__global__ void k_prefix() {
    if (threadIdx.x == 0) {
        int s = 0, t = 0;
        for (int e = 0; e < EE; e++) {
            g_base[e] = s;      s += g_cnt[e];
            g_tileStart[e] = t; t += (g_cnt[e] + 255) >> 8;
        }
        g_tileStart[EE] = t;
    }
}

// ---------------- scatter ----------------
__global__ void k_scatter() {
    int pix = blockIdx.x * 256 + threadIdx.x;
#pragma unroll
    for (int k = 0; k < 2; k++) {
        int e = g_top_idx[pix * 2 + k];
        int pos = atomicAdd(&g_cursor[e], 1);
        int at = g_base[e] + pos;
        g_listPix[at] = pix;
        g_listW[at]   = g_top_w[pix * 2 + k];
    }
}

// ---------------- main conv: mma.sync bf16 3-pass, M=256 tiles ----------------
#define MMA(c, a, b0, b1) \
    asm volatile("mma.sync.aligned.m16n8k16.row.col.f32.bf16.bf16.f32 " \
        "{%0,%1,%2,%3}, {%4,%5,%6,%7}, {%8,%9}, {%0,%1,%2,%3};" \
        : "+f"((c)[0]), "+f"((c)[1]), "+f"((c)[2]), "+f"((c)[3]) \
        : "r"((a)[0]), "r"((a)[1]), "r"((a)[2]), "r"((a)[3]), "r"(b0), "r"(b1))

#define LDSM4(r, addr) \
    asm volatile("ldmatrix.sync.aligned.m8n8.x4.shared.b16 {%0,%1,%2,%3}, [%4];" \
        : "=r"((r)[0]), "=r"((r)[1]), "=r"((r)[2]), "=r"((r)[3]) : "r"(addr))

__global__ void __launch_bounds__(256, 2)
k_conv(const float* __restrict__ expert_b, float* __restrict__ out) {
    extern __shared__ char sm[];
    const int tid = threadIdx.x, warp = tid >> 5, lane = tid & 31;

    int tile = blockIdx.x;
    if (tile >= g_tileStart[EE]) return;

    int e = 0;
    while (g_tileStart[e + 1] <= tile) e++;
    int r0 = (tile - g_tileStart[e]) << 8;
    int m  = g_cnt[e] - r0; if (m > 256) m = 256;
    int lb = g_base[e] + r0;

    // per-row: padded row index + gate weight
    {
        int valid = tid < m;
        int idx = lb + (valid ? tid : 0);
        int pix = g_listPix[idx];
        float gv = valid ? g_listW[idx] : 0.0f;
        int row = PADW + 1;   // interior (0,0): all taps in-bounds
        if (valid) {
            int b = pix >> 14, hw = pix & (HW - 1);
            row = b * PADIMG + ((hw >> 7) + 1) * PADW + ((hw & 127) + 1);
        }
        ((int*)(sm + PR_OFF))[tid]   = row;
        ((float*)(sm + GW_OFF))[tid] = gv;
    }
    if (tid < 64) ((float*)(sm + BIAS_OFF))[tid] = expert_b[(e << 6) + tid];
    __syncthreads();

    const int rbase = ((int*)(sm + PR_OFF))[tid];
    const uint4* __restrict__ wf = g_wf + (size_t)e * WF4E;

    float c[2][8][4];
#pragma unroll
    for (int h = 0; h < 2; h++)
#pragma unroll
        for (int nb = 0; nb < 8; nb++)
#pragma unroll
            for (int j = 0; j < 4; j++) c[h][nb][j] = 0.0f;

    // ldmatrix base addresses (shared-space u32)
    unsigned smb = (unsigned)__cvta_generic_to_shared(sm);
    unsigned lrow = (warp << 5) + (lane & 15);
    unsigned aHb0 = smb + AHI_OFF + lrow * 144 + ((lane >> 4) << 4);
    unsigned aHb1 = aHb0 + 16 * 144;
    unsigned aLb0 = aHb0 + (ALO_OFF - AHI_OFF);
    unsigned aLb1 = aHb1 + (ALO_OFF - AHI_OFF);

#pragma unroll 1
    for (int t = 0; t < 9; t++) {
        __syncthreads();   // previous tap consumed
        // ---- A gather: each thread one row, 128B hi + 128B lo ----
        {
            int row = rbase + (t / 3 - 1) * PADW + (t % 3 - 1);
            const uint4* srcH = (const uint4*)(g_x_hi + ((size_t)row << 6));
            const uint4* srcL = (const uint4*)(g_x_lo + ((size_t)row << 6));
            char* aH = sm + AHI_OFF + tid * 144;
            char* aL = sm + ALO_OFF + tid * 144;
#pragma unroll
            for (int i = 0; i < 8; i++) {
                *(uint4*)(aH + i * 16) = srcH[i];
                *(uint4*)(aL + i * 16) = srcL[i];
            }
        }
        // ---- B stage: 16KB interleaved fragments ----
        {
            uint4* bf = (uint4*)(sm + BF_OFF);
            const uint4* src = wf + (t << 10);
#pragma unroll
            for (int i = 0; i < 4; i++)
                bf[tid + (i << 8)] = src[tid + (i << 8)];
        }
        __syncthreads();

        // ---- compute: 4 kc x 8 nb x (2 m-halves x 3 passes) ----
#pragma unroll
        for (int kc = 0; kc < 4; kc++) {
            unsigned ah0[4], ah1[4], al0[4], al1[4];
            LDSM4(ah0, aHb0 + kc * 32);
            LDSM4(ah1, aHb1 + kc * 32);
            LDSM4(al0, aLb0 + kc * 32);
            LDSM4(al1, aLb1 + kc * 32);
            const uint4* bp = (const uint4*)(sm + BF_OFF) + (kc << 8) + lane;
#pragma unroll
            for (int nb = 0; nb < 8; nb++) {
                uint4 bb = bp[nb << 5];
                MMA(c[0][nb], ah0, bb.x, bb.y);
                MMA(c[0][nb], ah0, bb.z, bb.w);
                MMA(c[0][nb], al0, bb.x, bb.y);
                MMA(c[1][nb], ah1, bb.x, bb.y);
                MMA(c[1][nb], ah1, bb.z, bb.w);
                MMA(c[1][nb], al1, bb.x, bb.y);
            }
        }
    }

    // ---- epilogue: gate-weight * (acc + bias) -> atomicAdd ----
    {
        const float* bias = (const float*)(sm + BIAS_OFF);
        int i4 = lane & 3;
#pragma unroll
        for (int h = 0; h < 2; h++) {
            int r1 = (warp << 5) + (h << 4) + (lane >> 2), r2 = r1 + 8;
            bool v1 = r1 < m, v2 = r2 < m;
            int pix1 = v1 ? g_listPix[lb + r1] : 0;
            int pix2 = v2 ? g_listPix[lb + r2] : 0;
            float gw1 = ((float*)(sm + GW_OFF))[r1];
            float gw2 = ((float*)(sm + GW_OFF))[r2];
            float* op1 = out + ((size_t)(pix1 >> 14) << 20) + (pix1 & (HW - 1));
            float* op2 = out + ((size_t)(pix2 >> 14) << 20) + (pix2 & (HW - 1));
#pragma unroll
            for (int nb = 0; nb < 8; nb++) {
                int co = nb * 8 + 2 * i4;
                if (v1) {
                    atomicAdd(op1 + ((size_t)co << 14),       gw1 * (c[h][nb][0] + bias[co]));
                    atomicAdd(op1 + ((size_t)(co + 1) << 14), gw1 * (c[h][nb][1] + bias[co + 1]));
                }
                if (v2) {
                    atomicAdd(op2 + ((size_t)co << 14),       gw2 * (c[h][nb][2] + bias[co]));
                    atomicAdd(op2 + ((size_t)(co + 1) << 14), gw2 * (c[h][nb][3] + bias[co + 1]));
                }
            }
        }
    }
}

// ---------------- relu ----------------
__global__ void k_relu(float* out, int n) {
    int i = blockIdx.x * 256 + threadIdx.x;
    if (i < n) out[i] = fmaxf(out[i], 0.0f);
}

extern "C" void kernel_launch(void* const* d_in, const int* in_sizes, int n_in,
                              void* d_out, int out_size) {
    const float* x        = (const float*)d_in[0];
    const float* expert_w = (const float*)d_in[1];
    const float* expert_b = (const float*)d_in[2];
    const float* gate_w   = (const float*)d_in[3];
    const float* gate_b   = (const float*)d_in[4];
    float* out = (float*)d_out;

    cudaFuncSetAttribute(k_conv, cudaFuncAttributeMaxDynamicSharedMemorySize,
                         CONV_SMEM);

    int n = NPIX * CC;

    k_init<<<(n + 255) / 256, 256>>>(out, n);
    k_tx<<<dim3(HW / 32, BB), dim3(32, 8)>>>(x);
    k_border<<<(NPADROW * 32 + 255) / 256, 256>>>();
    k_tw<<<(EE * WF4E + 255) / 256, 256>>>(expert_w);
    k_gate<<<NPIX / 256, 256>>>(x, gate_w, gate_b);
    k_prefix<<<1, 32>>>();
    k_scatter<<<NPIX / 256, 256>>>();
    k_conv<<<MAXTILES, 256, CONV_SMEM>>>(expert_b, out);
    k_relu<<<(n + 255) / 256, 256>>>(out, n);
}

// round 7
// speedup vs baseline: 1.0927x; 1.0927x over previous
#include <cuda_runtime.h>
#include <cuda_bf16.h>
#include <math.h>

// ---------------- problem constants ----------------
#define BB 4
#define CC 64
#define HH 128
#define WW 128
#define EE 32
#define HW (HH*WW)              // 16384
#define NPIX (BB*HW)            // 65536
#define NASSIGN (NPIX*2)        // 131072
#define PADW 130
#define PADIMG (PADW*PADW)      // 16900
#define NPADROW (BB*PADIMG)     // 67600
#define MAXTILES 1056

// per-expert B fragments: 9 taps * 4 kc * 8 nb * 32 lanes uint4 {h0,h1,l0,l1}
#define WF4E 9216

// conv smem layout (byte offsets). A rows padded to 144B.
// stage s in {0,1}: AHI at s*18432, ALO at 36864+s*18432, B at 73728+s*16384
#define AHI_OFF 0u
#define ALO_OFF 36864u
#define BF_OFF  73728u
#define PR_OFF  106496u         // int[128]
#define GW_OFF  107008u         // float[128]
#define BIAS_OFF 107520u        // float[64]
#define CONV_SMEM 107776u

// ---------------- device scratch ----------------
__device__ __nv_bfloat16 g_x_hi[NPADROW * CC];
__device__ __nv_bfloat16 g_x_lo[NPADROW * CC];
__device__ uint4 g_wf[EE * WF4E];
__device__ int   g_top_idx[NPIX * 2];
__device__ float g_top_w[NPIX * 2];
__device__ int   g_cnt[EE];
__device__ int   g_base[EE];
__device__ int   g_cursor[EE];
__device__ int   g_tileStart[EE + 1];
__device__ int   g_listPix[NASSIGN];
__device__ float g_listW[NASSIGN];

__device__ __forceinline__ unsigned short bfbits(__nv_bfloat16 h) {
    return *reinterpret_cast<unsigned short*>(&h);
}

// ---------------- init ----------------
__global__ void k_init(float* out, int n) {
    int i = blockIdx.x * blockDim.x + threadIdx.x;
    if (i < n) out[i] = 0.0f;
    if (blockIdx.x == 0 && threadIdx.x < EE) {
        g_cnt[threadIdx.x] = 0;
        g_cursor[threadIdx.x] = 0;
    }
}

// ---------------- x -> padded channels-last bf16 hi/lo ----------------
__global__ void k_tx(const float* __restrict__ x) {
    __shared__ float s[CC][33];
    int b = blockIdx.y;
    int hw0 = blockIdx.x * 32;
    int tx = threadIdx.x, ty = threadIdx.y;
    for (int c = ty; c < CC; c += 8)
        s[c][tx] = x[((size_t)(b * CC + c) << 14) + hw0 + tx];
    __syncthreads();
    int t = ty * 32 + tx;
    int y = hw0 >> 7, x0 = hw0 & 127;
    unsigned* hi32 = (unsigned*)g_x_hi;
    unsigned* lo32 = (unsigned*)g_x_lo;
    for (int k = t; k < 32 * 32; k += 256) {
        int p = k >> 5, cp = k & 31;
        int row = b * PADIMG + (y + 1) * PADW + (x0 + p + 1);
        float a = s[2 * cp][p], bv = s[2 * cp + 1][p];
        __nv_bfloat16 ha = __float2bfloat16_rn(a), hb = __float2bfloat16_rn(bv);
        float la = a - __bfloat162float(ha), lb = bv - __bfloat162float(hb);
        __nv_bfloat16 hla = __float2bfloat16_rn(la), hlb = __float2bfloat16_rn(lb);
        hi32[row * 32 + cp] = ((unsigned)bfbits(hb) << 16) | bfbits(ha);
        lo32[row * 32 + cp] = ((unsigned)bfbits(hlb) << 16) | bfbits(hla);
    }
}

// ---------------- zero the halo rows ----------------
__global__ void k_border() {
    int w = blockIdx.x * 256 + threadIdx.x;
    if (w >= NPADROW * 32) return;
    int p = w >> 5;
    int r = p % PADIMG;
    int y = r / PADW, xx = r % PADW;
    if (y == 0 || y == PADW - 1 || xx == 0 || xx == PADW - 1) {
        ((unsigned*)g_x_hi)[w] = 0u;
        ((unsigned*)g_x_lo)[w] = 0u;
    }
}

// ---------------- weights -> pre-permuted interleaved B fragments ----------------
__global__ void k_tw(const float* __restrict__ w) {
    int i = blockIdx.x * 256 + threadIdx.x;
    if (i >= EE * WF4E) return;
    int e = i / WF4E;
    int r = i % WF4E;
    int t = r >> 10;  r &= 1023;
    int kc = r >> 8;  r &= 255;
    int nb = r >> 5;
    int lane = r & 31;
    int co  = nb * 8 + (lane >> 2);
    int ci0 = kc * 16 + 2 * (lane & 3);
    const float* wp = w + (size_t)(((e << 6) | co) << 6) * 9 + t;
    float v00 = wp[(ci0)     * 9], v01 = wp[(ci0 + 1) * 9];
    float v10 = wp[(ci0 + 8) * 9], v11 = wp[(ci0 + 9) * 9];
    __nv_bfloat16 h00 = __float2bfloat16_rn(v00), h01 = __float2bfloat16_rn(v01);
    __nv_bfloat16 h10 = __float2bfloat16_rn(v10), h11 = __float2bfloat16_rn(v11);
    uint4 o;
    o.x = ((unsigned)bfbits(h01) << 16) | bfbits(h00);
    o.y = ((unsigned)bfbits(h11) << 16) | bfbits(h10);
    o.z = ((unsigned)bfbits(__float2bfloat16_rn(v01 - __bfloat162float(h01))) << 16)
        | bfbits(__float2bfloat16_rn(v00 - __bfloat162float(h00)));
    o.w = ((unsigned)bfbits(__float2bfloat16_rn(v11 - __bfloat162float(h11))) << 16)
        | bfbits(__float2bfloat16_rn(v10 - __bfloat162float(h10)));
    g_wf[i] = o;
}

// ---------------- gate (fp32, smem-staged) ----------------
__global__ void __launch_bounds__(256) k_gate(const float* __restrict__ x,
                                              const float* __restrict__ gw,
                                              const float* __restrict__ gb) {
    __shared__ float gws[EE * CC];
    __shared__ float gbs[EE];
    __shared__ float xs[16][256];
    int tid = threadIdx.x;
    for (int i = tid; i < EE * CC; i += 256) gws[i] = gw[i];
    if (tid < EE) gbs[tid] = gb[tid];

    int pix0 = blockIdx.x * 256;
    int b = pix0 >> 14, hw0 = pix0 & (HW - 1);

    float lg[EE];
#pragma unroll
    for (int e = 0; e < EE; e++) lg[e] = 0.0f;

    for (int c0 = 0; c0 < CC; c0 += 16) {
        __syncthreads();
        for (int i = tid; i < 16 * 256; i += 256)
            xs[i >> 8][tid] = x[((size_t)(b * CC + c0 + (i >> 8)) << 14) + hw0 + tid];
        __syncthreads();
#pragma unroll 4
        for (int c = 0; c < 16; c++) {
            float xv = xs[c][tid];
#pragma unroll
            for (int e = 0; e < EE; e++)
                lg[e] = fmaf(xv, gws[(e << 6) + c0 + c], lg[e]);
        }
    }
#pragma unroll
    for (int e = 0; e < EE; e++) lg[e] += gbs[e];

    float v1 = -1e30f; int i1 = 0;
#pragma unroll
    for (int e = 0; e < EE; e++) if (lg[e] > v1) { v1 = lg[e]; i1 = e; }
    float v2 = -1e30f; int i2 = 0;
#pragma unroll
    for (int e = 0; e < EE; e++) if (e != i1 && lg[e] > v2) { v2 = lg[e]; i2 = e; }

    float d = expf(v2 - v1);
    float s = 1.0f / (1.0f + d);
    int pix = pix0 + tid;
    g_top_idx[pix * 2]     = i1;
    g_top_idx[pix * 2 + 1] = i2;
    g_top_w[pix * 2]       = s;
    g_top_w[pix * 2 + 1]   = d * s;
    atomicAdd(&g_cnt[i1], 1);
    atomicAdd(&g_cnt[i2], 1);
}

// ---------------- prefix ----------------
__global__ void k_prefix() {
    if (threadIdx.x == 0) {
        int s = 0, t = 0;
        for (int e = 0; e < EE; e++) {
            g_base[e] = s;      s += g_cnt[e];
            g_tileStart[e] = t; t += (g_cnt[e] + 127) >> 7;
        }
        g_tileStart[EE] = t;
    }
}

// ---------------- scatter ----------------
__global__ void k_scatter() {
    int pix = blockIdx.x * 256 + threadIdx.x;
#pragma unroll
    for (int k = 0; k < 2; k++) {
        int e = g_top_idx[pix * 2 + k];
        int pos = atomicAdd(&g_cursor[e], 1);
        int at = g_base[e] + pos;
        g_listPix[at] = pix;
        g_listW[at]   = g_top_w[pix * 2 + k];
    }
}

// ---------------- main conv: cp.async double-buffered, mma bf16 3-pass ----------------
#define MMA(c, a, b0, b1) \
    asm volatile("mma.sync.aligned.m16n8k16.row.col.f32.bf16.bf16.f32 " \
        "{%0,%1,%2,%3}, {%4,%5,%6,%7}, {%8,%9}, {%0,%1,%2,%3};" \
        : "+f"((c)[0]), "+f"((c)[1]), "+f"((c)[2]), "+f"((c)[3]) \
        : "r"((a)[0]), "r"((a)[1]), "r"((a)[2]), "r"((a)[3]), "r"(b0), "r"(b1))

#define LDSM4(r, addr) \
    asm volatile("ldmatrix.sync.aligned.m8n8.x4.shared.b16 {%0,%1,%2,%3}, [%4];" \
        : "=r"((r)[0]), "=r"((r)[1]), "=r"((r)[2]), "=r"((r)[3]) : "r"(addr))

#define CPA16(dst, src) \
    asm volatile("cp.async.cg.shared.global [%0], [%1], 16;" :: "r"(dst), "l"(src))

__global__ void __launch_bounds__(256, 2)
k_conv(const float* __restrict__ expert_b, float* __restrict__ out) {
    extern __shared__ char sm[];
    const int tid = threadIdx.x, warp = tid >> 5, lane = tid & 31;

    int tile = blockIdx.x;
    if (tile >= g_tileStart[EE]) return;

    int e = 0;
    while (g_tileStart[e + 1] <= tile) e++;
    int r0 = (tile - g_tileStart[e]) << 7;
    int m  = g_cnt[e] - r0; if (m > 128) m = 128;
    int lb = g_base[e] + r0;

    if (tid < 128) {
        int valid = tid < m;
        int idx = lb + (valid ? tid : 0);
        int pix = g_listPix[idx];
        float gv = valid ? g_listW[idx] : 0.0f;
        int row = PADW + 1;   // interior (0,0): all taps in-bounds
        if (valid) {
            int b = pix >> 14, hw = pix & (HW - 1);
            row = b * PADIMG + ((hw >> 7) + 1) * PADW + ((hw & 127) + 1);
        }
        ((int*)(sm + PR_OFF))[tid]   = row;
        ((float*)(sm + GW_OFF))[tid] = gv;
    }
    if (tid < 64) ((float*)(sm + BIAS_OFF))[tid] = expert_b[(e << 6) + tid];
    __syncthreads();

    const int myrow = tid >> 1, half = tid & 1;
    const int rbase = ((int*)(sm + PR_OFF))[myrow];
    const uint4* __restrict__ wf = g_wf + (size_t)e * WF4E;
    unsigned smb = (unsigned)__cvta_generic_to_shared(sm);

    // cp.async destination bases (stage-invariant parts)
    unsigned aHdst = smb + AHI_OFF + myrow * 144 + half * 64;
    unsigned aLdst = smb + ALO_OFF + myrow * 144 + half * 64;
    unsigned bdst  = smb + BF_OFF + tid * 16;

    float c[8][4];
#pragma unroll
    for (int nb = 0; nb < 8; nb++)
#pragma unroll
        for (int j = 0; j < 4; j++) c[nb][j] = 0.0f;

    // ldmatrix source addresses
    unsigned lrow = (warp << 4) + (lane & 15);
    unsigned aHb = smb + AHI_OFF + lrow * 144 + ((lane >> 4) << 4);
    unsigned aLb = aHb + (ALO_OFF - AHI_OFF);

    // ---- issue stage for tap tt into buffer s ----
    auto issue = [&](int tt, int s) {
        int row = rbase + (tt / 3 - 1) * PADW + (tt % 3 - 1);
        const char* srcH = (const char*)(g_x_hi + ((size_t)row << 6)) + half * 64;
        const char* srcL = (const char*)(g_x_lo + ((size_t)row << 6)) + half * 64;
        unsigned dH = aHdst + s * 18432u;
        unsigned dL = aLdst + s * 18432u;
#pragma unroll
        for (int i = 0; i < 4; i++) {
            CPA16(dH + i * 16, srcH + i * 16);
            CPA16(dL + i * 16, srcL + i * 16);
        }
        const char* srcB = (const char*)(wf + (tt << 10)) + tid * 16;
        unsigned dB = bdst + s * 16384u;
#pragma unroll
        for (int i = 0; i < 4; i++)
            CPA16(dB + i * 4096, srcB + i * 4096);
        asm volatile("cp.async.commit_group;");
    };

    issue(0, 0);

#pragma unroll 1
    for (int t = 0; t < 9; t++) {
        int s = t & 1;
        if (t < 8) issue(t + 1, s ^ 1);
        if (t < 8) asm volatile("cp.async.wait_group 1;");
        else       asm volatile("cp.async.wait_group 0;");
        __syncthreads();

        unsigned aH = aHb + s * 18432u;
        unsigned aL = aLb + s * 18432u;
        const uint4* bp0 = (const uint4*)(sm + BF_OFF + s * 16384u) + lane;
#pragma unroll
        for (int kc = 0; kc < 4; kc++) {
            unsigned ah[4], al[4];
            LDSM4(ah, aH + kc * 32);
            LDSM4(al, aL + kc * 32);
            const uint4* bp = bp0 + (kc << 8);
#pragma unroll
            for (int nb = 0; nb < 8; nb++) {
                uint4 bb = bp[nb << 5];
                MMA(c[nb], ah, bb.x, bb.y);
                MMA(c[nb], ah, bb.z, bb.w);
                MMA(c[nb], al, bb.x, bb.y);
            }
        }
        if (t < 8) __syncthreads();   // buffer s free before t+1 issues into it
    }

    // ---- epilogue ----
    {
        const float* bias = (const float*)(sm + BIAS_OFF);
        int i4 = lane & 3;
        int r1 = (warp << 4) + (lane >> 2), r2 = r1 + 8;
        bool v1 = r1 < m, v2 = r2 < m;
        int pix1 = v1 ? g_listPix[lb + r1] : 0;
        int pix2 = v2 ? g_listPix[lb + r2] : 0;
        float gw1 = ((float*)(sm + GW_OFF))[r1];
        float gw2 = ((float*)(sm + GW_OFF))[r2];
        float* op1 = out + ((size_t)(pix1 >> 14) << 20) + (pix1 & (HW - 1));
        float* op2 = out + ((size_t)(pix2 >> 14) << 20) + (pix2 & (HW - 1));
#pragma unroll
        for (int nb = 0; nb < 8; nb++) {
            int co = nb * 8 + 2 * i4;
            if (v1) {
                atomicAdd(op1 + ((size_t)co << 14),       gw1 * (c[nb][0] + bias[co]));
                atomicAdd(op1 + ((size_t)(co + 1) << 14), gw1 * (c[nb][1] + bias[co + 1]));
            }
            if (v2) {
                atomicAdd(op2 + ((size_t)co << 14),       gw2 * (c[nb][2] + bias[co]));
                atomicAdd(op2 + ((size_t)(co + 1) << 14), gw2 * (c[nb][3] + bias[co + 1]));
            }
        }
    }
}

// ---------------- relu ----------------
__global__ void k_relu(float* out, int n) {
    int i = blockIdx.x * 256 + threadIdx.x;
    if (i < n) out[i] = fmaxf(out[i], 0.0f);
}

extern "C" void kernel_launch(void* const* d_in, const int* in_sizes, int n_in,
                              void* d_out, int out_size) {
    const float* x        = (const float*)d_in[0];
    const float* expert_w = (const float*)d_in[1];
    const float* expert_b = (const float*)d_in[2];
    const float* gate_w   = (const float*)d_in[3];
    const float* gate_b   = (const float*)d_in[4];
    float* out = (float*)d_out;

    cudaFuncSetAttribute(k_conv, cudaFuncAttributeMaxDynamicSharedMemorySize,
                         CONV_SMEM);

    int n = NPIX * CC;

    k_init<<<(n + 255) / 256, 256>>>(out, n);
    k_tx<<<dim3(HW / 32, BB), dim3(32, 8)>>>(x);
    k_border<<<(NPADROW * 32 + 255) / 256, 256>>>();
    k_tw<<<(EE * WF4E + 255) / 256, 256>>>(expert_w);
    k_gate<<<NPIX / 256, 256>>>(x, gate_w, gate_b);
    k_prefix<<<1, 32>>>();
    k_scatter<<<NPIX / 256, 256>>>();
    k_conv<<<MAXTILES, 256, CONV_SMEM>>>(expert_b, out);
    k_relu<<<(n + 255) / 256, 256>>>(out, n);
}

// round 8
// speedup vs baseline: 1.2025x; 1.1004x over previous
#include <cuda_runtime.h>
#include <cuda_bf16.h>
#include <math.h>

// ---------------- problem constants ----------------
#define BB 4
#define CC 64
#define HH 128
#define WW 128
#define EE 32
#define HW (HH*WW)              // 16384
#define NPIX (BB*HW)            // 65536
#define PADW 130
#define PADIMG (PADW*PADW)      // 16900
#define NPADROW (BB*PADIMG)     // 67600
#define MAXTILES 1056
#define SLAB 65536              // per-expert assignment slab

// per-expert B fragments: 9 taps * 4 kc * 8 nb * 32 lanes uint4 {h0,h1,l0,l1}
#define WF4E 9216

// conv smem layout (byte offsets). A rows 144B pitch.
#define AHI_OFF 0u
#define ALO_OFF 36864u
#define BF_OFF  73728u
#define PR_OFF  106496u         // int[128]
#define GW_OFF  107008u         // float[128]
#define BIAS_OFF 107520u        // float[64]
#define CONV_SMEM 107776u

// prep phase block ranges
#define PB_TX   2048
#define PB_OUT  (PB_TX + 4096)
#define PB_BRD  (PB_OUT + 516)
#define PB_TW   (PB_BRD + 1152)
#define PB_ALL  (PB_TW + 1)

// ---------------- device scratch ----------------
__device__ __nv_bfloat16 g_x_hi[NPADROW * CC];
__device__ __nv_bfloat16 g_x_lo[NPADROW * CC];
__device__ uint4 g_wf[EE * WF4E];
__device__ int   g_top_idx[NPIX * 2];
__device__ float g_top_w[NPIX * 2];
__device__ int   g_cnt[EE];
__device__ int   g_cursor[EE];
__device__ int   g_listPix[EE * SLAB];
__device__ float g_listW[EE * SLAB];

__device__ __forceinline__ unsigned short bfbits(__nv_bfloat16 h) {
    return *reinterpret_cast<unsigned short*>(&h);
}

// ---------------- fused prep: tx + out-zero + border + tw + counters ----------------
__global__ void __launch_bounds__(256) k_prep(const float* __restrict__ x,
                                              const float* __restrict__ w,
                                              float* __restrict__ out) {
    int blk = blockIdx.x, tid = threadIdx.x;
    if (blk < PB_TX) {
        // transpose+split x: one 32-pixel chunk per block
        __shared__ float s[CC][33];
        int b = blk >> 9, hw0 = (blk & 511) << 5;
        int tx = tid & 31, ty = tid >> 5;     // 32 x 8
        for (int c = ty; c < CC; c += 8)
            s[c][tx] = x[((size_t)(b * CC + c) << 14) + hw0 + tx];
        __syncthreads();
        int y = hw0 >> 7, x0 = hw0 & 127;
        unsigned* hi32 = (unsigned*)g_x_hi;
        unsigned* lo32 = (unsigned*)g_x_lo;
        for (int k = tid; k < 32 * 32; k += 256) {
            int p = k >> 5, cp = k & 31;
            int row = b * PADIMG + (y + 1) * PADW + (x0 + p + 1);
            float a = s[2 * cp][p], bv = s[2 * cp + 1][p];
            __nv_bfloat16 ha = __float2bfloat16_rn(a), hb = __float2bfloat16_rn(bv);
            float la = a - __bfloat162float(ha), lb = bv - __bfloat162float(hb);
            hi32[row * 32 + cp] = ((unsigned)bfbits(hb) << 16) | bfbits(ha);
            lo32[row * 32 + cp] = ((unsigned)bfbits(__float2bfloat16_rn(lb)) << 16)
                                | bfbits(__float2bfloat16_rn(la));
        }
    } else if (blk < PB_OUT) {
        // zero output: 1,048,576 float4
        ((float4*)out)[(blk - PB_TX) * 256 + tid] = make_float4(0.f, 0.f, 0.f, 0.f);
    } else if (blk < PB_BRD) {
        // zero halo: 2064 border pixels * 64 words
        int u = (blk - PB_OUT) * 256 + tid;     // 132,096 = 2064*64
        int word = u & 63;
        int p = u >> 6;
        int b = p / 516, r = p % 516;
        int y, xx;
        if (r < 130)      { y = 0;          xx = r; }
        else if (r < 260) { y = 129;        xx = r - 130; }
        else if (r < 388) { y = r - 260 + 1; xx = 0; }
        else              { y = r - 388 + 1; xx = 129; }
        int row = b * PADIMG + y * PADW + xx;
        if (word < 32) ((unsigned*)g_x_hi)[row * 32 + word] = 0u;
        else           ((unsigned*)g_x_lo)[row * 32 + (word - 32)] = 0u;
    } else if (blk < PB_TW) {
        // weights -> pre-permuted interleaved B fragments
        int i = (blk - PB_BRD) * 256 + tid;     // EE*WF4E = 294,912
        int e = i / WF4E;
        int r = i % WF4E;
        int t = r >> 10;  r &= 1023;
        int kc = r >> 8;  r &= 255;
        int nb = r >> 5;
        int lane = r & 31;
        int co  = nb * 8 + (lane >> 2);
        int ci0 = kc * 16 + 2 * (lane & 3);
        const float* wp = w + (size_t)(((e << 6) | co) << 6) * 9 + t;
        float v00 = wp[(ci0)     * 9], v01 = wp[(ci0 + 1) * 9];
        float v10 = wp[(ci0 + 8) * 9], v11 = wp[(ci0 + 9) * 9];
        __nv_bfloat16 h00 = __float2bfloat16_rn(v00), h01 = __float2bfloat16_rn(v01);
        __nv_bfloat16 h10 = __float2bfloat16_rn(v10), h11 = __float2bfloat16_rn(v11);
        uint4 o;
        o.x = ((unsigned)bfbits(h01) << 16) | bfbits(h00);
        o.y = ((unsigned)bfbits(h11) << 16) | bfbits(h10);
        o.z = ((unsigned)bfbits(__float2bfloat16_rn(v01 - __bfloat162float(h01))) << 16)
            | bfbits(__float2bfloat16_rn(v00 - __bfloat162float(h00)));
        o.w = ((unsigned)bfbits(__float2bfloat16_rn(v11 - __bfloat162float(h11))) << 16)
            | bfbits(__float2bfloat16_rn(v10 - __bfloat162float(h10)));
        g_wf[i] = o;
    } else {
        if (tid < EE) { g_cnt[tid] = 0; g_cursor[tid] = 0; }
    }
}

// ---------------- gate (fp32, smem-staged) ----------------
__global__ void __launch_bounds__(256) k_gate(const float* __restrict__ x,
                                              const float* __restrict__ gw,
                                              const float* __restrict__ gb) {
    __shared__ float gws[EE * CC];
    __shared__ float gbs[EE];
    __shared__ float xs[16][256];
    int tid = threadIdx.x;
    for (int i = tid; i < EE * CC; i += 256) gws[i] = gw[i];
    if (tid < EE) gbs[tid] = gb[tid];

    int pix0 = blockIdx.x * 256;
    int b = pix0 >> 14, hw0 = pix0 & (HW - 1);

    float lg[EE];
#pragma unroll
    for (int e = 0; e < EE; e++) lg[e] = 0.0f;

    for (int c0 = 0; c0 < CC; c0 += 16) {
        __syncthreads();
        for (int i = tid; i < 16 * 256; i += 256)
            xs[i >> 8][tid] = x[((size_t)(b * CC + c0 + (i >> 8)) << 14) + hw0 + tid];
        __syncthreads();
#pragma unroll 4
        for (int c = 0; c < 16; c++) {
            float xv = xs[c][tid];
#pragma unroll
            for (int e = 0; e < EE; e++)
                lg[e] = fmaf(xv, gws[(e << 6) + c0 + c], lg[e]);
        }
    }
#pragma unroll
    for (int e = 0; e < EE; e++) lg[e] += gbs[e];

    float v1 = -1e30f; int i1 = 0;
#pragma unroll
    for (int e = 0; e < EE; e++) if (lg[e] > v1) { v1 = lg[e]; i1 = e; }
    float v2 = -1e30f; int i2 = 0;
#pragma unroll
    for (int e = 0; e < EE; e++) if (e != i1 && lg[e] > v2) { v2 = lg[e]; i2 = e; }

    float d = expf(v2 - v1);
    float s = 1.0f / (1.0f + d);
    int pix = pix0 + tid;
    g_top_idx[pix * 2]     = i1;
    g_top_idx[pix * 2 + 1] = i2;
    g_top_w[pix * 2]       = s;
    g_top_w[pix * 2 + 1]   = d * s;
    atomicAdd(&g_cnt[i1], 1);
    atomicAdd(&g_cnt[i2], 1);
}

// ---------------- scatter into per-expert slabs ----------------
__global__ void k_scatter() {
    int pix = blockIdx.x * 256 + threadIdx.x;
#pragma unroll
    for (int k = 0; k < 2; k++) {
        int e = g_top_idx[pix * 2 + k];
        int pos = atomicAdd(&g_cursor[e], 1);
        int at = e * SLAB + pos;
        g_listPix[at] = pix;
        g_listW[at]   = g_top_w[pix * 2 + k];
    }
}

// ---------------- main conv: cp.async pipelined, mma bf16 3-pass, 4m x 2n split ----------------
#define MMA(c, a, b0, b1) \
    asm volatile("mma.sync.aligned.m16n8k16.row.col.f32.bf16.bf16.f32 " \
        "{%0,%1,%2,%3}, {%4,%5,%6,%7}, {%8,%9}, {%0,%1,%2,%3};" \
        : "+f"((c)[0]), "+f"((c)[1]), "+f"((c)[2]), "+f"((c)[3]) \
        : "r"((a)[0]), "r"((a)[1]), "r"((a)[2]), "r"((a)[3]), "r"(b0), "r"(b1))

#define LDSM4(r, addr) \
    asm volatile("ldmatrix.sync.aligned.m8n8.x4.shared.b16 {%0,%1,%2,%3}, [%4];" \
        : "=r"((r)[0]), "=r"((r)[1]), "=r"((r)[2]), "=r"((r)[3]) : "r"(addr))

#define CPA16(dst, src) \
    asm volatile("cp.async.cg.shared.global [%0], [%1], 16;" :: "r"(dst), "l"(src))

__global__ void __launch_bounds__(256, 2)
k_conv(const float* __restrict__ expert_b, float* __restrict__ out) {
    extern __shared__ char sm[];
    const int tid = threadIdx.x, warp = tid >> 5, lane = tid & 31;

    // locate (expert, tile offset) from blockIdx
    int tile = blockIdx.x;
    int e = 0, acc = 0, r0 = -1;
    for (; e < EE; e++) {
        int nt = (g_cnt[e] + 127) >> 7;
        if (tile < acc + nt) { r0 = (tile - acc) << 7; break; }
        acc += nt;
    }
    if (r0 < 0) return;
    int m  = g_cnt[e] - r0; if (m > 128) m = 128;
    int lb = e * SLAB + r0;

    if (tid < 128) {
        int valid = tid < m;
        int idx = lb + (valid ? tid : 0);
        int pix = g_listPix[idx];
        float gv = valid ? g_listW[idx] : 0.0f;
        int row = PADW + 1;   // interior (0,0): all taps in-bounds
        if (valid) {
            int b = pix >> 14, hw = pix & (HW - 1);
            row = b * PADIMG + ((hw >> 7) + 1) * PADW + ((hw & 127) + 1);
        }
        ((int*)(sm + PR_OFF))[tid]   = row;
        ((float*)(sm + GW_OFF))[tid] = gv;
    }
    if (tid < 64) ((float*)(sm + BIAS_OFF))[tid] = expert_b[(e << 6) + tid];
    __syncthreads();

    const int myrow = tid >> 1, half = tid & 1;
    const int rbase = ((int*)(sm + PR_OFF))[myrow];
    const uint4* __restrict__ wf = g_wf + (size_t)e * WF4E;
    unsigned smb = (unsigned)__cvta_generic_to_shared(sm);

    unsigned aHdst = smb + AHI_OFF + myrow * 144 + half * 64;
    unsigned aLdst = smb + ALO_OFF + myrow * 144 + half * 64;
    unsigned bdst  = smb + BF_OFF + tid * 16;

    // 4m x 2n warp split
    const int mt2 = warp & 3, nw = warp >> 2;
    float c[2][4][4];
#pragma unroll
    for (int h = 0; h < 2; h++)
#pragma unroll
        for (int nb = 0; nb < 4; nb++)
#pragma unroll
            for (int j = 0; j < 4; j++) c[h][nb][j] = 0.0f;

    unsigned lrow = (mt2 << 5) + (lane & 15);
    unsigned aHb0 = smb + AHI_OFF + lrow * 144 + ((lane >> 4) << 4);
    unsigned aHb1 = aHb0 + 16 * 144;
    unsigned aLb0 = aHb0 + (ALO_OFF - AHI_OFF);
    unsigned aLb1 = aHb1 + (ALO_OFF - AHI_OFF);

    auto issue = [&](int tt, int s) {
        int row = rbase + (tt / 3 - 1) * PADW + (tt % 3 - 1);
        const char* srcH = (const char*)(g_x_hi + ((size_t)row << 6)) + half * 64;
        const char* srcL = (const char*)(g_x_lo + ((size_t)row << 6)) + half * 64;
        unsigned dH = aHdst + s * 18432u;
        unsigned dL = aLdst + s * 18432u;
#pragma unroll
        for (int i = 0; i < 4; i++) {
            CPA16(dH + i * 16, srcH + i * 16);
            CPA16(dL + i * 16, srcL + i * 16);
        }
        const char* srcB = (const char*)(wf + (tt << 10)) + tid * 16;
        unsigned dB = bdst + s * 16384u;
#pragma unroll
        for (int i = 0; i < 4; i++)
            CPA16(dB + i * 4096, srcB + i * 4096);
        asm volatile("cp.async.commit_group;");
    };

    issue(0, 0);

#pragma unroll 1
    for (int t = 0; t < 9; t++) {
        int s = t & 1;
        if (t < 8) issue(t + 1, s ^ 1);
        if (t < 8) asm volatile("cp.async.wait_group 1;");
        else       asm volatile("cp.async.wait_group 0;");
        __syncthreads();

        unsigned aH0 = aHb0 + s * 18432u, aH1 = aHb1 + s * 18432u;
        unsigned aL0 = aLb0 + s * 18432u, aL1 = aLb1 + s * 18432u;
        const uint4* bp0 = (const uint4*)(sm + BF_OFF + s * 16384u) + (nw << 7) + lane;
#pragma unroll
        for (int kc = 0; kc < 4; kc++) {
            unsigned ah0[4], ah1[4], al0[4], al1[4];
            LDSM4(ah0, aH0 + kc * 32);
            LDSM4(ah1, aH1 + kc * 32);
            LDSM4(al0, aL0 + kc * 32);
            LDSM4(al1, aL1 + kc * 32);
            const uint4* bp = bp0 + (kc << 8);
#pragma unroll
            for (int nb = 0; nb < 4; nb++) {
                uint4 bb = bp[nb << 5];
                MMA(c[0][nb], ah0, bb.x, bb.y);
                MMA(c[0][nb], ah0, bb.z, bb.w);
                MMA(c[0][nb], al0, bb.x, bb.y);
                MMA(c[1][nb], ah1, bb.x, bb.y);
                MMA(c[1][nb], ah1, bb.z, bb.w);
                MMA(c[1][nb], al1, bb.x, bb.y);
            }
        }
        if (t < 8) __syncthreads();
    }

    // ---- epilogue ----
    {
        const float* bias = (const float*)(sm + BIAS_OFF);
        int i4 = lane & 3;
#pragma unroll
        for (int h = 0; h < 2; h++) {
            int r1 = (mt2 << 5) + (h << 4) + (lane >> 2), r2 = r1 + 8;
            bool v1 = r1 < m, v2 = r2 < m;
            int pix1 = v1 ? g_listPix[lb + r1] : 0;
            int pix2 = v2 ? g_listPix[lb + r2] : 0;
            float gw1 = ((float*)(sm + GW_OFF))[r1];
            float gw2 = ((float*)(sm + GW_OFF))[r2];
            float* op1 = out + ((size_t)(pix1 >> 14) << 20) + (pix1 & (HW - 1));
            float* op2 = out + ((size_t)(pix2 >> 14) << 20) + (pix2 & (HW - 1));
#pragma unroll
            for (int nb = 0; nb < 4; nb++) {
                int co = ((nw << 2) + nb) * 8 + 2 * i4;
                if (v1) {
                    atomicAdd(op1 + ((size_t)co << 14),       gw1 * (c[h][nb][0] + bias[co]));
                    atomicAdd(op1 + ((size_t)(co + 1) << 14), gw1 * (c[h][nb][1] + bias[co + 1]));
                }
                if (v2) {
                    atomicAdd(op2 + ((size_t)co << 14),       gw2 * (c[h][nb][2] + bias[co]));
                    atomicAdd(op2 + ((size_t)(co + 1) << 14), gw2 * (c[h][nb][3] + bias[co + 1]));
                }
            }
        }
    }
}

// ---------------- relu ----------------
__global__ void k_relu(float* out, int n) {
    int i = blockIdx.x * 256 + threadIdx.x;
    if (i < n) out[i] = fmaxf(out[i], 0.0f);
}

extern "C" void kernel_launch(void* const* d_in, const int* in_sizes, int n_in,
                              void* d_out, int out_size) {
    const float* x        = (const float*)d_in[0];
    const float* expert_w = (const float*)d_in[1];
    const float* expert_b = (const float*)d_in[2];
    const float* gate_w   = (const float*)d_in[3];
    const float* gate_b   = (const float*)d_in[4];
    float* out = (float*)d_out;

    cudaFuncSetAttribute(k_conv, cudaFuncAttributeMaxDynamicSharedMemorySize,
                         CONV_SMEM);

    int n = NPIX * CC;

    k_prep<<<PB_ALL, 256>>>(x, expert_w, out);
    k_gate<<<NPIX / 256, 256>>>(x, gate_w, gate_b);
    k_scatter<<<NPIX / 256, 256>>>();
    k_conv<<<MAXTILES, 256, CONV_SMEM>>>(expert_b, out);   // launch #4 -> profiled
    k_relu<<<(n + 255) / 256, 256>>>(out, n);
}

// round 9
// speedup vs baseline: 1.4885x; 1.2378x over previous
#include <cuda_runtime.h>
#include <cuda_fp16.h>
#include <math.h>

// ---------------- problem constants ----------------
#define BB 4
#define CC 64
#define HH 128
#define WW 128
#define EE 32
#define HW (HH*WW)              // 16384
#define NPIX (BB*HW)            // 65536
#define PADW 130
#define PADIMG (PADW*PADW)      // 16900
#define NPADROW (BB*PADIMG)     // 67600
#define MAXTILES 1056
#define SLAB 65536              // per-expert assignment slab

// per-expert B fragments: 9 taps * 4 kc * 8 nb * 32 lanes uint4 {h0,h1,l0,l1}
#define WF4E 9216

// conv smem layout (byte offsets). A rows 144B pitch, hi-only, 2 stages.
#define AHI_OFF 0u              // 2 x 18432
#define BF_OFF  36864u          // 2 x 16384
#define PR_OFF  69632u          // int[128]
#define GW_OFF  70144u          // float[128]
#define BIAS_OFF 70656u         // float[64]
#define CONV_SMEM 70912u

// prep phase block ranges
#define PB_TX   2048
#define PB_OUT  (PB_TX + 4096)
#define PB_BRD  (PB_OUT + 258)
#define PB_TW   (PB_BRD + 1152)
#define PB_ALL  (PB_TW + 1)

// ---------------- device scratch ----------------
__device__ __half g_x_hi[NPADROW * CC];
__device__ uint4 g_wf[EE * WF4E];
__device__ int   g_top_idx[NPIX * 2];
__device__ float g_top_w[NPIX * 2];
__device__ int   g_cnt[EE];
__device__ int   g_cursor[EE];
__device__ int   g_listPix[EE * SLAB];
__device__ float g_listW[EE * SLAB];

__device__ __forceinline__ unsigned short hfbits(__half h) {
    return *reinterpret_cast<unsigned short*>(&h);
}

// ---------------- fused prep: tx + out-zero + border + tw + counters ----------------
__global__ void __launch_bounds__(256) k_prep(const float* __restrict__ x,
                                              const float* __restrict__ w,
                                              float* __restrict__ out) {
    int blk = blockIdx.x, tid = threadIdx.x;
    if (blk < PB_TX) {
        // transpose x -> padded channels-last fp16 (hi only)
        __shared__ float s[CC][33];
        int b = blk >> 9, hw0 = (blk & 511) << 5;
        int tx = tid & 31, ty = tid >> 5;
        for (int c = ty; c < CC; c += 8)
            s[c][tx] = x[((size_t)(b * CC + c) << 14) + hw0 + tx];
        __syncthreads();
        int y = hw0 >> 7, x0 = hw0 & 127;
        unsigned* hi32 = (unsigned*)g_x_hi;
        for (int k = tid; k < 32 * 32; k += 256) {
            int p = k >> 5, cp = k & 31;
            int row = b * PADIMG + (y + 1) * PADW + (x0 + p + 1);
            __half ha = __float2half_rn(s[2 * cp][p]);
            __half hb = __float2half_rn(s[2 * cp + 1][p]);
            hi32[row * 32 + cp] = ((unsigned)hfbits(hb) << 16) | hfbits(ha);
        }
    } else if (blk < PB_OUT) {
        ((float4*)out)[(blk - PB_TX) * 256 + tid] = make_float4(0.f, 0.f, 0.f, 0.f);
    } else if (blk < PB_BRD) {
        // zero halo: 2064 border pixels * 32 words
        int u = (blk - PB_OUT) * 256 + tid;     // < 66048
        if (u < 2064 * 32) {
            int word = u & 31;
            int p = u >> 5;
            int b = p / 516, r = p % 516;
            int y, xx;
            if (r < 130)      { y = 0;           xx = r; }
            else if (r < 260) { y = 129;         xx = r - 130; }
            else if (r < 388) { y = r - 260 + 1; xx = 0; }
            else              { y = r - 388 + 1; xx = 129; }
            int row = b * PADIMG + y * PADW + xx;
            ((unsigned*)g_x_hi)[row * 32 + word] = 0u;
        }
    } else if (blk < PB_TW) {
        // weights -> pre-permuted interleaved fp16 B fragments {hi k0-pair, hi k8-pair, lo, lo}
        int i = (blk - PB_BRD) * 256 + tid;     // EE*WF4E = 294,912
        int e = i / WF4E;
        int r = i % WF4E;
        int t = r >> 10;  r &= 1023;
        int kc = r >> 8;  r &= 255;
        int nb = r >> 5;
        int lane = r & 31;
        int co  = nb * 8 + (lane >> 2);
        int ci0 = kc * 16 + 2 * (lane & 3);
        const float* wp = w + (size_t)(((e << 6) | co) << 6) * 9 + t;
        float v00 = wp[(ci0)     * 9], v01 = wp[(ci0 + 1) * 9];
        float v10 = wp[(ci0 + 8) * 9], v11 = wp[(ci0 + 9) * 9];
        __half h00 = __float2half_rn(v00), h01 = __float2half_rn(v01);
        __half h10 = __float2half_rn(v10), h11 = __float2half_rn(v11);
        uint4 o;
        o.x = ((unsigned)hfbits(h01) << 16) | hfbits(h00);
        o.y = ((unsigned)hfbits(h11) << 16) | hfbits(h10);
        o.z = ((unsigned)hfbits(__float2half_rn(v01 - __half2float(h01))) << 16)
            | hfbits(__float2half_rn(v00 - __half2float(h00)));
        o.w = ((unsigned)hfbits(__float2half_rn(v11 - __half2float(h11))) << 16)
            | hfbits(__float2half_rn(v10 - __half2float(h10)));
        g_wf[i] = o;
    } else {
        if (tid < EE) { g_cnt[tid] = 0; g_cursor[tid] = 0; }
    }
}

// ---------------- gate (fp32, smem-staged) ----------------
__global__ void __launch_bounds__(256) k_gate(const float* __restrict__ x,
                                              const float* __restrict__ gw,
                                              const float* __restrict__ gb) {
    __shared__ float gws[EE * CC];
    __shared__ float gbs[EE];
    __shared__ float xs[16][256];
    int tid = threadIdx.x;
    for (int i = tid; i < EE * CC; i += 256) gws[i] = gw[i];
    if (tid < EE) gbs[tid] = gb[tid];

    int pix0 = blockIdx.x * 256;
    int b = pix0 >> 14, hw0 = pix0 & (HW - 1);

    float lg[EE];
#pragma unroll
    for (int e = 0; e < EE; e++) lg[e] = 0.0f;

    for (int c0 = 0; c0 < CC; c0 += 16) {
        __syncthreads();
        for (int i = tid; i < 16 * 256; i += 256)
            xs[i >> 8][tid] = x[((size_t)(b * CC + c0 + (i >> 8)) << 14) + hw0 + tid];
        __syncthreads();
#pragma unroll 4
        for (int c = 0; c < 16; c++) {
            float xv = xs[c][tid];
#pragma unroll
            for (int e = 0; e < EE; e++)
                lg[e] = fmaf(xv, gws[(e << 6) + c0 + c], lg[e]);
        }
    }
#pragma unroll
    for (int e = 0; e < EE; e++) lg[e] += gbs[e];

    float v1 = -1e30f; int i1 = 0;
#pragma unroll
    for (int e = 0; e < EE; e++) if (lg[e] > v1) { v1 = lg[e]; i1 = e; }
    float v2 = -1e30f; int i2 = 0;
#pragma unroll
    for (int e = 0; e < EE; e++) if (e != i1 && lg[e] > v2) { v2 = lg[e]; i2 = e; }

    float d = expf(v2 - v1);
    float s = 1.0f / (1.0f + d);
    int pix = pix0 + tid;
    g_top_idx[pix * 2]     = i1;
    g_top_idx[pix * 2 + 1] = i2;
    g_top_w[pix * 2]       = s;
    g_top_w[pix * 2 + 1]   = d * s;
    atomicAdd(&g_cnt[i1], 1);
    atomicAdd(&g_cnt[i2], 1);
}

// ---------------- scatter into per-expert slabs ----------------
__global__ void k_scatter() {
    int pix = blockIdx.x * 256 + threadIdx.x;
#pragma unroll
    for (int k = 0; k < 2; k++) {
        int e = g_top_idx[pix * 2 + k];
        int pos = atomicAdd(&g_cursor[e], 1);
        int at = e * SLAB + pos;
        g_listPix[at] = pix;
        g_listW[at]   = g_top_w[pix * 2 + k];
    }
}

// ---------------- main conv: fp16 2-pass, 3 CTA/SM, cp.async pipelined ----------------
#define MMA(c, a, b0, b1) \
    asm volatile("mma.sync.aligned.m16n8k16.row.col.f32.f16.f16.f32 " \
        "{%0,%1,%2,%3}, {%4,%5,%6,%7}, {%8,%9}, {%0,%1,%2,%3};" \
        : "+f"((c)[0]), "+f"((c)[1]), "+f"((c)[2]), "+f"((c)[3]) \
        : "r"((a)[0]), "r"((a)[1]), "r"((a)[2]), "r"((a)[3]), "r"(b0), "r"(b1))

#define LDSM4(r, addr) \
    asm volatile("ldmatrix.sync.aligned.m8n8.x4.shared.b16 {%0,%1,%2,%3}, [%4];" \
        : "=r"((r)[0]), "=r"((r)[1]), "=r"((r)[2]), "=r"((r)[3]) : "r"(addr))

#define CPA16(dst, src) \
    asm volatile("cp.async.cg.shared.global [%0], [%1], 16;" :: "r"(dst), "l"(src))

__global__ void __launch_bounds__(256, 3)
k_conv(const float* __restrict__ expert_b, float* __restrict__ out) {
    extern __shared__ char sm[];
    const int tid = threadIdx.x, warp = tid >> 5, lane = tid & 31;

    int tile = blockIdx.x;
    int e = 0, acc = 0, r0 = -1;
    for (; e < EE; e++) {
        int nt = (g_cnt[e] + 127) >> 7;
        if (tile < acc + nt) { r0 = (tile - acc) << 7; break; }
        acc += nt;
    }
    if (r0 < 0) return;
    int m  = g_cnt[e] - r0; if (m > 128) m = 128;
    int lb = e * SLAB + r0;

    if (tid < 128) {
        int valid = tid < m;
        int idx = lb + (valid ? tid : 0);
        int pix = g_listPix[idx];
        float gv = valid ? g_listW[idx] : 0.0f;
        int row = PADW + 1;   // interior (0,0): all taps in-bounds
        if (valid) {
            int b = pix >> 14, hw = pix & (HW - 1);
            row = b * PADIMG + ((hw >> 7) + 1) * PADW + ((hw & 127) + 1);
        }
        ((int*)(sm + PR_OFF))[tid]   = row;
        ((float*)(sm + GW_OFF))[tid] = gv;
    }
    if (tid < 64) ((float*)(sm + BIAS_OFF))[tid] = expert_b[(e << 6) + tid];
    __syncthreads();

    const int myrow = tid >> 1, half = tid & 1;
    const int rbase = ((int*)(sm + PR_OFF))[myrow];
    const uint4* __restrict__ wf = g_wf + (size_t)e * WF4E;
    unsigned smb = (unsigned)__cvta_generic_to_shared(sm);

    unsigned aHdst = smb + AHI_OFF + myrow * 144 + half * 64;
    unsigned bdst  = smb + BF_OFF + tid * 16;

    // 4m x 2n warp split
    const int mt2 = warp & 3, nw = warp >> 2;
    float c[2][4][4];
#pragma unroll
    for (int h = 0; h < 2; h++)
#pragma unroll
        for (int nb = 0; nb < 4; nb++)
#pragma unroll
            for (int j = 0; j < 4; j++) c[h][nb][j] = 0.0f;

    unsigned lrow = (mt2 << 5) + (lane & 15);
    unsigned aHb0 = smb + AHI_OFF + lrow * 144 + ((lane >> 4) << 4);
    unsigned aHb1 = aHb0 + 16 * 144;

    auto issue = [&](int tt, int s) {
        int row = rbase + (tt / 3 - 1) * PADW + (tt % 3 - 1);
        const char* srcH = (const char*)(g_x_hi + ((size_t)row << 6)) + half * 64;
        unsigned dH = aHdst + s * 18432u;
#pragma unroll
        for (int i = 0; i < 4; i++)
            CPA16(dH + i * 16, srcH + i * 16);
        const char* srcB = (const char*)(wf + (tt << 10)) + tid * 16;
        unsigned dB = bdst + s * 16384u;
#pragma unroll
        for (int i = 0; i < 4; i++)
            CPA16(dB + i * 4096, srcB + i * 4096);
        asm volatile("cp.async.commit_group;");
    };

    issue(0, 0);

#pragma unroll 1
    for (int t = 0; t < 9; t++) {
        int s = t & 1;
        if (t < 8) issue(t + 1, s ^ 1);
        if (t < 8) asm volatile("cp.async.wait_group 1;");
        else       asm volatile("cp.async.wait_group 0;");
        __syncthreads();

        unsigned aH0 = aHb0 + s * 18432u, aH1 = aHb1 + s * 18432u;
        const uint4* bp0 = (const uint4*)(sm + BF_OFF + s * 16384u) + (nw << 7) + lane;
#pragma unroll
        for (int kc = 0; kc < 4; kc++) {
            unsigned ah0[4], ah1[4];
            LDSM4(ah0, aH0 + kc * 32);
            LDSM4(ah1, aH1 + kc * 32);
            const uint4* bp = bp0 + (kc << 8);
#pragma unroll
            for (int nb = 0; nb < 4; nb++) {
                uint4 bb = bp[nb << 5];
                MMA(c[0][nb], ah0, bb.x, bb.y);
                MMA(c[0][nb], ah0, bb.z, bb.w);
                MMA(c[1][nb], ah1, bb.x, bb.y);
                MMA(c[1][nb], ah1, bb.z, bb.w);
            }
        }
        if (t < 8) __syncthreads();
    }

    // ---- epilogue ----
    {
        const float* bias = (const float*)(sm + BIAS_OFF);
        int i4 = lane & 3;
#pragma unroll
        for (int h = 0; h < 2; h++) {
            int r1 = (mt2 << 5) + (h << 4) + (lane >> 2), r2 = r1 + 8;
            bool v1 = r1 < m, v2 = r2 < m;
            int pix1 = v1 ? g_listPix[lb + r1] : 0;
            int pix2 = v2 ? g_listPix[lb + r2] : 0;
            float gw1 = ((float*)(sm + GW_OFF))[r1];
            float gw2 = ((float*)(sm + GW_OFF))[r2];
            float* op1 = out + ((size_t)(pix1 >> 14) << 20) + (pix1 & (HW - 1));
            float* op2 = out + ((size_t)(pix2 >> 14) << 20) + (pix2 & (HW - 1));
#pragma unroll
            for (int nb = 0; nb < 4; nb++) {
                int co = ((nw << 2) + nb) * 8 + 2 * i4;
                if (v1) {
                    atomicAdd(op1 + ((size_t)co << 14),       gw1 * (c[h][nb][0] + bias[co]));
                    atomicAdd(op1 + ((size_t)(co + 1) << 14), gw1 * (c[h][nb][1] + bias[co + 1]));
                }
                if (v2) {
                    atomicAdd(op2 + ((size_t)co << 14),       gw2 * (c[h][nb][2] + bias[co]));
                    atomicAdd(op2 + ((size_t)(co + 1) << 14), gw2 * (c[h][nb][3] + bias[co + 1]));
                }
            }
        }
    }
}

// ---------------- relu ----------------
__global__ void k_relu(float* out, int n) {
    int i = blockIdx.x * 256 + threadIdx.x;
    if (i < n) out[i] = fmaxf(out[i], 0.0f);
}

extern "C" void kernel_launch(void* const* d_in, const int* in_sizes, int n_in,
                              void* d_out, int out_size) {
    const float* x        = (const float*)d_in[0];
    const float* expert_w = (const float*)d_in[1];
    const float* expert_b = (const float*)d_in[2];
    const float* gate_w   = (const float*)d_in[3];
    const float* gate_b   = (const float*)d_in[4];
    float* out = (float*)d_out;

    cudaFuncSetAttribute(k_conv, cudaFuncAttributeMaxDynamicSharedMemorySize,
                         CONV_SMEM);

    int n = NPIX * CC;

    k_prep<<<PB_ALL, 256>>>(x, expert_w, out);
    k_gate<<<NPIX / 256, 256>>>(x, gate_w, gate_b);
    k_scatter<<<NPIX / 256, 256>>>();
    k_conv<<<MAXTILES, 256, CONV_SMEM>>>(expert_b, out);   // launch #4 -> profiled
    k_relu<<<(n + 255) / 256, 256>>>(out, n);
}

// round 10
// speedup vs baseline: 1.5531x; 1.0434x over previous
#include <cuda_runtime.h>
#include <cuda_fp16.h>
#include <math.h>

// ---------------- problem constants ----------------
#define BB 4
#define CC 64
#define HH 128
#define WW 128
#define EE 32
#define HW (HH*WW)              // 16384
#define NPIX (BB*HW)            // 65536
#define PADW 130
#define PADIMG (PADW*PADW)      // 16900
#define NPADROW (BB*PADIMG)     // 67600
#define MAXTILES 1056
#define SLAB 65536              // per-expert assignment slab

// per-expert B fragments: 9 taps * 4 kc * 8 nb * 32 lanes uint4 {h0,h1,l0,l1}
#define WF4E 9216

// conv smem layout. A: 128 rows x 400B pitch (384B data), single buffer.
#define AHI_OFF 0u              // 51200
#define PR_OFF  51200u          // int[128]
#define GW_OFF  51712u          // float[128]
#define BIAS_OFF 52224u         // float[64]
#define CONV_SMEM 52480u

// prep phase block ranges
#define PB_TX   2048
#define PB_OUT  (PB_TX + 4096)
#define PB_BRD  (PB_OUT + 258)
#define PB_TW   (PB_BRD + 1152)
#define PB_ALL  (PB_TW + 1)

// ---------------- device scratch ----------------
__device__ __half g_x_hi[NPADROW * CC];
__device__ uint4 g_wf[EE * WF4E];
__device__ int   g_cursor[EE];           // doubles as final per-expert count
__device__ int   g_listPix[EE * SLAB];
__device__ float g_listW[EE * SLAB];

__device__ __forceinline__ unsigned short hfbits(__half h) {
    return *reinterpret_cast<unsigned short*>(&h);
}

// ---------------- fused prep: tx + out-zero + border + tw + counters ----------------
__global__ void __launch_bounds__(256) k_prep(const float* __restrict__ x,
                                              const float* __restrict__ w,
                                              float* __restrict__ out) {
    int blk = blockIdx.x, tid = threadIdx.x;
    if (blk < PB_TX) {
        __shared__ float s[CC][33];
        int b = blk >> 9, hw0 = (blk & 511) << 5;
        int tx = tid & 31, ty = tid >> 5;
        for (int c = ty; c < CC; c += 8)
            s[c][tx] = x[((size_t)(b * CC + c) << 14) + hw0 + tx];
        __syncthreads();
        int y = hw0 >> 7, x0 = hw0 & 127;
        unsigned* hi32 = (unsigned*)g_x_hi;
        for (int k = tid; k < 32 * 32; k += 256) {
            int p = k >> 5, cp = k & 31;
            int row = b * PADIMG + (y + 1) * PADW + (x0 + p + 1);
            __half ha = __float2half_rn(s[2 * cp][p]);
            __half hb = __float2half_rn(s[2 * cp + 1][p]);
            hi32[row * 32 + cp] = ((unsigned)hfbits(hb) << 16) | hfbits(ha);
        }
    } else if (blk < PB_OUT) {
        ((float4*)out)[(blk - PB_TX) * 256 + tid] = make_float4(0.f, 0.f, 0.f, 0.f);
    } else if (blk < PB_BRD) {
        int u = (blk - PB_OUT) * 256 + tid;
        if (u < 2064 * 32) {
            int word = u & 31;
            int p = u >> 5;
            int b = p / 516, r = p % 516;
            int y, xx;
            if (r < 130)      { y = 0;           xx = r; }
            else if (r < 260) { y = 129;         xx = r - 130; }
            else if (r < 388) { y = r - 260 + 1; xx = 0; }
            else              { y = r - 388 + 1; xx = 129; }
            int row = b * PADIMG + y * PADW + xx;
            ((unsigned*)g_x_hi)[row * 32 + word] = 0u;
        }
    } else if (blk < PB_TW) {
        // weights -> pre-permuted interleaved fp16 B fragments {hi,hi,lo,lo}
        int i = (blk - PB_BRD) * 256 + tid;
        int e = i / WF4E;
        int r = i % WF4E;
        int t = r >> 10;  r &= 1023;
        int kc = r >> 8;  r &= 255;
        int nb = r >> 5;
        int lane = r & 31;
        int co  = nb * 8 + (lane >> 2);
        int ci0 = kc * 16 + 2 * (lane & 3);
        const float* wp = w + (size_t)(((e << 6) | co) << 6) * 9 + t;
        float v00 = wp[(ci0)     * 9], v01 = wp[(ci0 + 1) * 9];
        float v10 = wp[(ci0 + 8) * 9], v11 = wp[(ci0 + 9) * 9];
        __half h00 = __float2half_rn(v00), h01 = __float2half_rn(v01);
        __half h10 = __float2half_rn(v10), h11 = __float2half_rn(v11);
        uint4 o;
        o.x = ((unsigned)hfbits(h01) << 16) | hfbits(h00);
        o.y = ((unsigned)hfbits(h11) << 16) | hfbits(h10);
        o.z = ((unsigned)hfbits(__float2half_rn(v01 - __half2float(h01))) << 16)
            | hfbits(__float2half_rn(v00 - __half2float(h00)));
        o.w = ((unsigned)hfbits(__float2half_rn(v11 - __half2float(h11))) << 16)
            | hfbits(__float2half_rn(v10 - __half2float(h10)));
        g_wf[i] = o;
    } else {
        if (tid < EE) g_cursor[tid] = 0;
    }
}

// ---------------- gate + fused scatter ----------------
__global__ void __launch_bounds__(256) k_gate(const float* __restrict__ x,
                                              const float* __restrict__ gw,
                                              const float* __restrict__ gb) {
    __shared__ float gws[EE * CC];
    __shared__ float gbs[EE];
    __shared__ float xs[16][256];
    int tid = threadIdx.x;
    for (int i = tid; i < EE * CC; i += 256) gws[i] = gw[i];
    if (tid < EE) gbs[tid] = gb[tid];

    int pix0 = blockIdx.x * 256;
    int b = pix0 >> 14, hw0 = pix0 & (HW - 1);

    float lg[EE];
#pragma unroll
    for (int e = 0; e < EE; e++) lg[e] = 0.0f;

    for (int c0 = 0; c0 < CC; c0 += 16) {
        __syncthreads();
        for (int i = tid; i < 16 * 256; i += 256)
            xs[i >> 8][tid] = x[((size_t)(b * CC + c0 + (i >> 8)) << 14) + hw0 + tid];
        __syncthreads();
#pragma unroll 4
        for (int c = 0; c < 16; c++) {
            float xv = xs[c][tid];
#pragma unroll
            for (int e = 0; e < EE; e++)
                lg[e] = fmaf(xv, gws[(e << 6) + c0 + c], lg[e]);
        }
    }
#pragma unroll
    for (int e = 0; e < EE; e++) lg[e] += gbs[e];

    // exact top-2, first-index-on-tie (matches lax.top_k)
    float v1 = -1e30f; int i1 = 0;
#pragma unroll
    for (int e = 0; e < EE; e++) if (lg[e] > v1) { v1 = lg[e]; i1 = e; }
    float v2 = -1e30f; int i2 = 0;
#pragma unroll
    for (int e = 0; e < EE; e++) if (e != i1 && lg[e] > v2) { v2 = lg[e]; i2 = e; }

    float d = expf(v2 - v1);
    float s = 1.0f / (1.0f + d);
    int pix = pix0 + tid;
    int p1 = atomicAdd(&g_cursor[i1], 1);
    g_listPix[i1 * SLAB + p1] = pix;
    g_listW[i1 * SLAB + p1]  = s;
    int p2 = atomicAdd(&g_cursor[i2], 1);
    g_listPix[i2 * SLAB + p2] = pix;
    g_listW[i2 * SLAB + p2]  = d * s;
}

// ---------------- main conv: fp16 2-pass, 3-row-group stages, B via LDG/L1 ----------------
#define MMA(c, a, b0, b1) \
    asm volatile("mma.sync.aligned.m16n8k16.row.col.f32.f16.f16.f32 " \
        "{%0,%1,%2,%3}, {%4,%5,%6,%7}, {%8,%9}, {%0,%1,%2,%3};" \
        : "+f"((c)[0]), "+f"((c)[1]), "+f"((c)[2]), "+f"((c)[3]) \
        : "r"((a)[0]), "r"((a)[1]), "r"((a)[2]), "r"((a)[3]), "r"(b0), "r"(b1))

#define LDSM4(r, addr) \
    asm volatile("ldmatrix.sync.aligned.m8n8.x4.shared.b16 {%0,%1,%2,%3}, [%4];" \
        : "=r"((r)[0]), "=r"((r)[1]), "=r"((r)[2]), "=r"((r)[3]) : "r"(addr))

#define CPA16(dst, src) \
    asm volatile("cp.async.cg.shared.global [%0], [%1], 16;" :: "r"(dst), "l"(src))

__global__ void __launch_bounds__(256, 4)
k_conv(const float* __restrict__ expert_b, float* __restrict__ out) {
    extern __shared__ char sm[];
    const int tid = threadIdx.x, warp = tid >> 5, lane = tid & 31;

    int tile = blockIdx.x;
    int e = 0, acc = 0, r0 = -1;
    for (; e < EE; e++) {
        int nt = (g_cursor[e] + 127) >> 7;
        if (tile < acc + nt) { r0 = (tile - acc) << 7; break; }
        acc += nt;
    }
    if (r0 < 0) return;
    int m  = g_cursor[e] - r0; if (m > 128) m = 128;
    int lb = e * SLAB + r0;

    if (tid < 128) {
        int valid = tid < m;
        int idx = lb + (valid ? tid : 0);
        int pix = g_listPix[idx];
        float gv = valid ? g_listW[idx] : 0.0f;
        int row = PADW + 1;   // interior (0,0): all windows in-bounds
        if (valid) {
            int b = pix >> 14, hw = pix & (HW - 1);
            row = b * PADIMG + ((hw >> 7) + 1) * PADW + ((hw & 127) + 1);
        }
        ((int*)(sm + PR_OFF))[tid]   = row;
        ((float*)(sm + GW_OFF))[tid] = gv;
    }
    if (tid < 64) ((float*)(sm + BIAS_OFF))[tid] = expert_b[(e << 6) + tid];
    __syncthreads();

    const int myrow = tid >> 1, half = tid & 1;
    const int rbase = ((int*)(sm + PR_OFF))[myrow];
    const uint4* __restrict__ wf = g_wf + (size_t)e * WF4E;
    unsigned smb = (unsigned)__cvta_generic_to_shared(sm);

    // cp.async dst: row myrow, 400B pitch, this thread's 192B half
    unsigned aDst = smb + AHI_OFF + myrow * 400 + half * 192;

    // 4m x 2n warp split
    const int mt2 = warp & 3, nw = warp >> 2;
    float c[2][4][4];
#pragma unroll
    for (int h = 0; h < 2; h++)
#pragma unroll
        for (int nb = 0; nb < 4; nb++)
#pragma unroll
            for (int j = 0; j < 4; j++) c[h][nb][j] = 0.0f;

    unsigned aB0 = smb + AHI_OFF + ((mt2 << 5) + (lane & 15)) * 400 + ((lane >> 4) << 4);
    unsigned aB1 = aB0 + 16 * 400;

#pragma unroll 1
    for (int dy = 0; dy < 3; dy++) {
        if (dy) __syncthreads();   // A buffer consumed
        // gather this dy's 3-tap window: 384B span starting at (row+dy-1, px-1)
        {
            const char* src = (const char*)g_x_hi
                + (((size_t)(rbase + (dy - 1) * PADW - 1)) << 7) + half * 192;
#pragma unroll
            for (int i = 0; i < 12; i++)
                CPA16(aDst + i * 16, src + i * 16);
            asm volatile("cp.async.commit_group;");
            asm volatile("cp.async.wait_group 0;");
        }
        __syncthreads();

#pragma unroll
        for (int dx = 0; dx < 3; dx++) {
            int t = dy * 3 + dx;
#pragma unroll
            for (int kc = 0; kc < 4; kc++) {
                unsigned ah0[4], ah1[4];
                LDSM4(ah0, aB0 + dx * 128 + kc * 32);
                LDSM4(ah1, aB1 + dx * 128 + kc * 32);
                const uint4* bp = wf + (t << 10) + (kc << 8) + (nw << 7) + lane;
#pragma unroll
                for (int nb = 0; nb < 4; nb++) {
                    uint4 bb = __ldg(bp + (nb << 5));
                    MMA(c[0][nb], ah0, bb.x, bb.y);
                    MMA(c[0][nb], ah0, bb.z, bb.w);
                    MMA(c[1][nb], ah1, bb.x, bb.y);
                    MMA(c[1][nb], ah1, bb.z, bb.w);
                }
            }
        }
    }

    // ---- epilogue ----
    {
        const float* bias = (const float*)(sm + BIAS_OFF);
        int i4 = lane & 3;
#pragma unroll
        for (int h = 0; h < 2; h++) {
            int r1 = (mt2 << 5) + (h << 4) + (lane >> 2), r2 = r1 + 8;
            bool v1 = r1 < m, v2 = r2 < m;
            int pix1 = v1 ? g_listPix[lb + r1] : 0;
            int pix2 = v2 ? g_listPix[lb + r2] : 0;
            float gw1 = ((float*)(sm + GW_OFF))[r1];
            float gw2 = ((float*)(sm + GW_OFF))[r2];
            float* op1 = out + ((size_t)(pix1 >> 14) << 20) + (pix1 & (HW - 1));
            float* op2 = out + ((size_t)(pix2 >> 14) << 20) + (pix2 & (HW - 1));
#pragma unroll
            for (int nb = 0; nb < 4; nb++) {
                int co = ((nw << 2) + nb) * 8 + 2 * i4;
                if (v1) {
                    atomicAdd(op1 + ((size_t)co << 14),       gw1 * (c[h][nb][0] + bias[co]));
                    atomicAdd(op1 + ((size_t)(co + 1) << 14), gw1 * (c[h][nb][1] + bias[co + 1]));
                }
                if (v2) {
                    atomicAdd(op2 + ((size_t)co << 14),       gw2 * (c[h][nb][2] + bias[co]));
                    atomicAdd(op2 + ((size_t)(co + 1) << 14), gw2 * (c[h][nb][3] + bias[co + 1]));
                }
            }
        }
    }
}

// ---------------- relu ----------------
__global__ void k_relu(float* out, int n) {
    int i = blockIdx.x * 256 + threadIdx.x;
    if (i < n) out[i] = fmaxf(out[i], 0.0f);
}

extern "C" void kernel_launch(void* const* d_in, const int* in_sizes, int n_in,
                              void* d_out, int out_size) {
    const float* x        = (const float*)d_in[0];
    const float* expert_w = (const float*)d_in[1];
    const float* expert_b = (const float*)d_in[2];
    const float* gate_w   = (const float*)d_in[3];
    const float* gate_b   = (const float*)d_in[4];
    float* out = (float*)d_out;

    cudaFuncSetAttribute(k_conv, cudaFuncAttributeMaxDynamicSharedMemorySize,
                         CONV_SMEM);

    int n = NPIX * CC;

    k_prep<<<PB_ALL, 256>>>(x, expert_w, out);
    k_gate<<<NPIX / 256, 256>>>(x, gate_w, gate_b);
    k_conv<<<MAXTILES, 256, CONV_SMEM>>>(expert_b, out);
    k_relu<<<(n + 255) / 256, 256>>>(out, n);
}

// round 12
// speedup vs baseline: 1.8199x; 1.1718x over previous
#include <cuda_runtime.h>
#include <cuda_fp16.h>
#include <math.h>

// ---------------- problem constants ----------------
#define BB 4
#define CC 64
#define HH 128
#define WW 128
#define EE 32
#define HW (HH*WW)              // 16384
#define NPIX (BB*HW)            // 65536
#define PADW 130
#define PADIMG (PADW*PADW)      // 16900
#define NPADROW (BB*PADIMG)     // 67600
#define MAXTILES 1056
#define SLAB 65536              // per-expert assignment slab

// per-expert B fragments: 9 taps * 4 kc * 8 nb * 32 lanes uint4 {h0,h1,l0,l1}
#define WF4E 9216

// conv smem layout. A: 128 rows x 400B pitch (384B data), single buffer.
#define AHI_OFF 0u              // 51200
#define PR_OFF  51200u          // int[128]
#define GW_OFF  51712u          // float[128]
#define BIAS_OFF 52224u         // float[64]
#define CONV_SMEM 52480u

// prep phase block ranges (out-zero phase removed)
#define PB_TX   2048
#define PB_BRD  (PB_TX + 258)
#define PB_TW   (PB_BRD + 1152)
#define PB_ALL  (PB_TW + 1)

// ---------------- device scratch ----------------
__device__ __half g_x_hi[NPADROW * CC];
__device__ uint4 g_wf[EE * WF4E];
__device__ int   g_cursor[EE];           // doubles as final per-expert count
__device__ int   g_listPix[EE * SLAB];   // stores pixk = pix*2+k
__device__ float g_listW[EE * SLAB];
__device__ float g_scr[NPIX * 2 * CC];   // per-assignment results [pixk][64]

__device__ __forceinline__ unsigned short hfbits(__half h) {
    return *reinterpret_cast<unsigned short*>(&h);
}

// ---------------- fused prep: tx + border + tw + counters ----------------
__global__ void __launch_bounds__(256) k_prep(const float* __restrict__ x,
                                              const float* __restrict__ w) {
    int blk = blockIdx.x, tid = threadIdx.x;
    if (blk < PB_TX) {
        __shared__ float s[CC][33];
        int b = blk >> 9, hw0 = (blk & 511) << 5;
        int tx = tid & 31, ty = tid >> 5;
        for (int c = ty; c < CC; c += 8)
            s[c][tx] = x[((size_t)(b * CC + c) << 14) + hw0 + tx];
        __syncthreads();
        int y = hw0 >> 7, x0 = hw0 & 127;
        unsigned* hi32 = (unsigned*)g_x_hi;
        for (int k = tid; k < 32 * 32; k += 256) {
            int p = k >> 5, cp = k & 31;
            int row = b * PADIMG + (y + 1) * PADW + (x0 + p + 1);
            __half ha = __float2half_rn(s[2 * cp][p]);
            __half hb = __float2half_rn(s[2 * cp + 1][p]);
            hi32[row * 32 + cp] = ((unsigned)hfbits(hb) << 16) | hfbits(ha);
        }
    } else if (blk < PB_BRD) {
        int u = (blk - PB_TX) * 256 + tid;
        if (u < 2064 * 32) {
            int word = u & 31;
            int p = u >> 5;
            int b = p / 516, r = p % 516;
            int y, xx;
            if (r < 130)      { y = 0;           xx = r; }
            else if (r < 260) { y = 129;         xx = r - 130; }
            else if (r < 388) { y = r - 260 + 1; xx = 0; }
            else              { y = r - 388 + 1; xx = 129; }
            int row = b * PADIMG + y * PADW + xx;
            ((unsigned*)g_x_hi)[row * 32 + word] = 0u;
        }
    } else if (blk < PB_TW) {
        // weights -> pre-permuted interleaved fp16 B fragments {hi,hi,lo,lo}
        int i = (blk - PB_BRD) * 256 + tid;
        int e = i / WF4E;
        int r = i % WF4E;
        int t = r >> 10;  r &= 1023;
        int kc = r >> 8;  r &= 255;
        int nb = r >> 5;
        int lane = r & 31;
        int co  = nb * 8 + (lane >> 2);
        int ci0 = kc * 16 + 2 * (lane & 3);
        const float* wp = w + (size_t)(((e << 6) | co) << 6) * 9 + t;
        float v00 = wp[(ci0)     * 9], v01 = wp[(ci0 + 1) * 9];
        float v10 = wp[(ci0 + 8) * 9], v11 = wp[(ci0 + 9) * 9];
        __half h00 = __float2half_rn(v00), h01 = __float2half_rn(v01);
        __half h10 = __float2half_rn(v10), h11 = __float2half_rn(v11);
        uint4 o;
        o.x = ((unsigned)hfbits(h01) << 16) | hfbits(h00);
        o.y = ((unsigned)hfbits(h11) << 16) | hfbits(h10);
        o.z = ((unsigned)hfbits(__float2half_rn(v01 - __half2float(h01))) << 16)
            | hfbits(__float2half_rn(v00 - __half2float(h00)));
        o.w = ((unsigned)hfbits(__float2half_rn(v11 - __half2float(h11))) << 16)
            | hfbits(__float2half_rn(v10 - __half2float(h10)));
        g_wf[i] = o;
    } else {
        if (tid < EE) g_cursor[tid] = 0;
    }
}

// ---------------- gate + fused scatter (appends pixk) ----------------
__global__ void __launch_bounds__(256) k_gate(const float* __restrict__ x,
                                              const float* __restrict__ gw,
                                              const float* __restrict__ gb) {
    __shared__ float gws[EE * CC];
    __shared__ float gbs[EE];
    __shared__ float xs[16][256];
    int tid = threadIdx.x;
    for (int i = tid; i < EE * CC; i += 256) gws[i] = gw[i];
    if (tid < EE) gbs[tid] = gb[tid];

    int pix0 = blockIdx.x * 256;
    int b = pix0 >> 14, hw0 = pix0 & (HW - 1);

    float lg[EE];
#pragma unroll
    for (int e = 0; e < EE; e++) lg[e] = 0.0f;

    for (int c0 = 0; c0 < CC; c0 += 16) {
        __syncthreads();
        for (int i = tid; i < 16 * 256; i += 256)
            xs[i >> 8][tid] = x[((size_t)(b * CC + c0 + (i >> 8)) << 14) + hw0 + tid];
        __syncthreads();
#pragma unroll 4
        for (int c = 0; c < 16; c++) {
            float xv = xs[c][tid];
#pragma unroll
            for (int e = 0; e < EE; e++)
                lg[e] = fmaf(xv, gws[(e << 6) + c0 + c], lg[e]);
        }
    }
#pragma unroll
    for (int e = 0; e < EE; e++) lg[e] += gbs[e];

    // exact top-2, first-index-on-tie (matches lax.top_k)
    float v1 = -1e30f; int i1 = 0;
#pragma unroll
    for (int e = 0; e < EE; e++) if (lg[e] > v1) { v1 = lg[e]; i1 = e; }
    float v2 = -1e30f; int i2 = 0;
#pragma unroll
    for (int e = 0; e < EE; e++) if (e != i1 && lg[e] > v2) { v2 = lg[e]; i2 = e; }

    float d = expf(v2 - v1);
    float s = 1.0f / (1.0f + d);
    int pix = pix0 + tid;
    int p1 = atomicAdd(&g_cursor[i1], 1);
    g_listPix[i1 * SLAB + p1] = pix * 2;
    g_listW[i1 * SLAB + p1]  = s;
    int p2 = atomicAdd(&g_cursor[i2], 1);
    g_listPix[i2 * SLAB + p2] = pix * 2 + 1;
    g_listW[i2 * SLAB + p2]  = d * s;
}

// ---------------- main conv: fp16 2-pass, 3-row-group stages, B via LDG/L1 ----------------
#define MMA(c, a, b0, b1) \
    asm volatile("mma.sync.aligned.m16n8k16.row.col.f32.f16.f16.f32 " \
        "{%0,%1,%2,%3}, {%4,%5,%6,%7}, {%8,%9}, {%0,%1,%2,%3};" \
        : "+f"((c)[0]), "+f"((c)[1]), "+f"((c)[2]), "+f"((c)[3]) \
        : "r"((a)[0]), "r"((a)[1]), "r"((a)[2]), "r"((a)[3]), "r"(b0), "r"(b1))

#define LDSM4(r, addr) \
    asm volatile("ldmatrix.sync.aligned.m8n8.x4.shared.b16 {%0,%1,%2,%3}, [%4];" \
        : "=r"((r)[0]), "=r"((r)[1]), "=r"((r)[2]), "=r"((r)[3]) : "r"(addr))

#define CPA16(dst, src) \
    asm volatile("cp.async.cg.shared.global [%0], [%1], 16;" :: "r"(dst), "l"(src))

__global__ void __launch_bounds__(256, 4)
k_conv(const float* __restrict__ expert_b) {
    extern __shared__ char sm[];
    const int tid = threadIdx.x, warp = tid >> 5, lane = tid & 31;

    int tile = blockIdx.x;
    int e = 0, acc = 0, r0 = -1;
    for (; e < EE; e++) {
        int nt = (g_cursor[e] + 127) >> 7;
        if (tile < acc + nt) { r0 = (tile - acc) << 7; break; }
        acc += nt;
    }
    if (r0 < 0) return;
    int m  = g_cursor[e] - r0; if (m > 128) m = 128;
    int lb = e * SLAB + r0;

    if (tid < 128) {
        int valid = tid < m;
        int idx = lb + (valid ? tid : 0);
        int pixk = g_listPix[idx];
        float gv = valid ? g_listW[idx] : 0.0f;
        int row = PADW + 1;   // interior (0,0): all windows in-bounds
        if (valid) {
            int pix = pixk >> 1;
            int b = pix >> 14, hw = pix & (HW - 1);
            row = b * PADIMG + ((hw >> 7) + 1) * PADW + ((hw & 127) + 1);
        }
        ((int*)(sm + PR_OFF))[tid]   = row;
        ((float*)(sm + GW_OFF))[tid] = gv;
    }
    if (tid < 64) ((float*)(sm + BIAS_OFF))[tid] = expert_b[(e << 6) + tid];
    __syncthreads();

    const int myrow = tid >> 1, half = tid & 1;
    const int rbase = ((int*)(sm + PR_OFF))[myrow];
    const uint4* __restrict__ wf = g_wf + (size_t)e * WF4E;
    unsigned smb = (unsigned)__cvta_generic_to_shared(sm);

    unsigned aDst = smb + AHI_OFF + myrow * 400 + half * 192;

    // 4m x 2n warp split
    const int mt2 = warp & 3, nw = warp >> 2;
    float c[2][4][4];
#pragma unroll
    for (int h = 0; h < 2; h++)
#pragma unroll
        for (int nb = 0; nb < 4; nb++)
#pragma unroll
            for (int j = 0; j < 4; j++) c[h][nb][j] = 0.0f;

    unsigned aB0 = smb + AHI_OFF + ((mt2 << 5) + (lane & 15)) * 400 + ((lane >> 4) << 4);
    unsigned aB1 = aB0 + 16 * 400;

#pragma unroll 1
    for (int dy = 0; dy < 3; dy++) {
        if (dy) __syncthreads();   // A buffer consumed
        {
            const char* src = (const char*)g_x_hi
                + (((size_t)(rbase + (dy - 1) * PADW - 1)) << 7) + half * 192;
#pragma unroll
            for (int i = 0; i < 12; i++)
                CPA16(aDst + i * 16, src + i * 16);
            asm volatile("cp.async.commit_group;");
            asm volatile("cp.async.wait_group 0;");
        }
        __syncthreads();

#pragma unroll
        for (int dx = 0; dx < 3; dx++) {
            int t = dy * 3 + dx;
#pragma unroll
            for (int kc = 0; kc < 4; kc++) {
                unsigned ah0[4], ah1[4];
                LDSM4(ah0, aB0 + dx * 128 + kc * 32);
                LDSM4(ah1, aB1 + dx * 128 + kc * 32);
                const uint4* bp = wf + (t << 10) + (kc << 8) + (nw << 7) + lane;
#pragma unroll
                for (int nb = 0; nb < 4; nb++) {
                    uint4 bb = __ldg(bp + (nb << 5));
                    MMA(c[0][nb], ah0, bb.x, bb.y);
                    MMA(c[0][nb], ah0, bb.z, bb.w);
                    MMA(c[1][nb], ah1, bb.x, bb.y);
                    MMA(c[1][nb], ah1, bb.z, bb.w);
                }
            }
        }
    }

    // ---- epilogue: plain stores of gw*(acc+bias) into per-assignment scratch ----
    {
        const float* bias = (const float*)(sm + BIAS_OFF);
        int i4 = lane & 3;
#pragma unroll
        for (int h = 0; h < 2; h++) {
            int r1 = (mt2 << 5) + (h << 4) + (lane >> 2), r2 = r1 + 8;
            bool v1 = r1 < m, v2 = r2 < m;
            int pk1 = v1 ? g_listPix[lb + r1] : 0;
            int pk2 = v2 ? g_listPix[lb + r2] : 0;
            float gw1 = ((float*)(sm + GW_OFF))[r1];
            float gw2 = ((float*)(sm + GW_OFF))[r2];
            float* sp1 = g_scr + ((size_t)pk1 << 6);
            float* sp2 = g_scr + ((size_t)pk2 << 6);
#pragma unroll
            for (int nb = 0; nb < 4; nb++) {
                int co = ((nw << 2) + nb) * 8 + 2 * i4;
                if (v1)
                    *(float2*)(sp1 + co) = make_float2(gw1 * (c[h][nb][0] + bias[co]),
                                                       gw1 * (c[h][nb][1] + bias[co + 1]));
                if (v2)
                    *(float2*)(sp2 + co) = make_float2(gw2 * (c[h][nb][2] + bias[co]),
                                                       gw2 * (c[h][nb][3] + bias[co + 1]));
            }
        }
    }
}

// ---------------- combine: sum 2 slots, relu, transpose to NCHW ----------------
__global__ void __launch_bounds__(256) k_comb(float* __restrict__ out) {
    __shared__ float s[64][68];
    int tid = threadIdx.x;
    int pix0 = blockIdx.x << 6;
    int b = pix0 >> 14, hw0 = pix0 & (HW - 1);

    // read: 4 threads per pixel, 16 channels each; sum slots, relu
    {
        int p = tid >> 2, c4 = (tid & 3) << 4;
        const float4* s0 = (const float4*)(g_scr + ((size_t)(pix0 + p) << 7)) + (c4 >> 2);
        const float4* s1 = (const float4*)(g_scr + ((size_t)(pix0 + p) << 7) + 64) + (c4 >> 2);
#pragma unroll
        for (int i = 0; i < 4; i++) {
            float4 a = s0[i], bv = s1[i];
            s[c4 + 4 * i + 0][p] = fmaxf(a.x + bv.x, 0.0f);
            s[c4 + 4 * i + 1][p] = fmaxf(a.y + bv.y, 0.0f);
            s[c4 + 4 * i + 2][p] = fmaxf(a.z + bv.z, 0.0f);
            s[c4 + 4 * i + 3][p] = fmaxf(a.w + bv.w, 0.0f);
        }
    }
    __syncthreads();
    // write: 4 threads per channel, 16 pixels each (coalesced NCHW)
    {
        int c = tid >> 2, p4 = (tid & 3) << 4;
        float* op = out + ((size_t)((b << 6) + c) << 14) + hw0 + p4;
#pragma unroll
        for (int i = 0; i < 4; i++)
            *(float4*)(op + 4 * i) = *(float4*)&s[c][p4 + 4 * i];
    }
}

extern "C" void kernel_launch(void* const* d_in, const int* in_sizes, int n_in,
                              void* d_out, int out_size) {
    const float* x        = (const float*)d_in[0];
    const float* expert_w = (const float*)d_in[1];
    const float* expert_b = (const float*)d_in[2];
    const float* gate_w   = (const float*)d_in[3];
    const float* gate_b   = (const float*)d_in[4];
    float* out = (float*)d_out;

    cudaFuncSetAttribute(k_conv, cudaFuncAttributeMaxDynamicSharedMemorySize,
                         CONV_SMEM);

    k_prep<<<PB_ALL, 256>>>(x, expert_w);
    k_gate<<<NPIX / 256, 256>>>(x, gate_w, gate_b);
    k_conv<<<MAXTILES, 256, CONV_SMEM>>>(expert_b);
    k_comb<<<NPIX / 64, 256>>>(out);
}